// round 2
// baseline (speedup 1.0000x reference)
#include <cuda_runtime.h>

#define HDIM 512
#define BATCH 256
#define TLEN 512
#define NSTEPS 511          // steps use trg[:, 0..510]
#define FC1_N 1024
#define FC2_N 32000

// -------- persistent device scratch (no allocations allowed) --------
__device__ float g_h[2][BATCH * HDIM];   // double-buffered hidden state
__device__ float g_c[BATCH * HDIM];      // cell state
__device__ float g_z[BATCH * FC1_N];     // fc1 output

// -------- packed fp32x2 helpers (Blackwell FFMA2 path) --------
__device__ __forceinline__ unsigned long long pack2(float lo, float hi) {
    unsigned long long r;
    asm("mov.b64 %0, {%1, %2};" : "=l"(r) : "f"(lo), "f"(hi));
    return r;
}
__device__ __forceinline__ void unpack2(unsigned long long v, float& lo, float& hi) {
    asm("mov.b64 {%0, %1}, %2;" : "=f"(lo), "=f"(hi) : "l"(v));
}
__device__ __forceinline__ void ffma2(unsigned long long& d,
                                      unsigned long long a, unsigned long long b) {
    asm("fma.rn.f32x2 %0, %1, %2, %0;" : "+l"(d) : "l"(a), "l"(b));
}

__device__ __forceinline__ float sigmoidf_(float x) {
    return 1.0f / (1.0f + expf(-x));          // saturates exactly to 0/1 at extremes
}
__device__ __forceinline__ float tanhf_(float x) {
    return 1.0f - 2.0f / (expf(2.0f * x) + 1.0f);  // -> +/-1 exactly at extremes
}

// -------- init: zero h[0] and c --------
__global__ void zero_state() {
    int i = blockIdx.x * blockDim.x + threadIdx.x;
    int stride = gridDim.x * blockDim.x;
    for (; i < BATCH * HDIM; i += stride) {
        g_h[0][i] = 0.0f;
        g_c[i] = 0.0f;
    }
}

// ============================================================================
// One LSTM timestep.
// Grid: (16 k-tiles, 8 batch-tiles), 256 threads.
// CTA computes gates tile: 32 batch rows x (4 gates x 32 k), K = 512.
// Thread (bg, cc): batch rows {b0+2bg, +1}, k columns {k0+2cc, k0+2cc+1},
// all 4 gates -> full pointwise c/h update stays in-register.
// ============================================================================
__global__ __launch_bounds__(256)
void lstm_step(const int* __restrict__ trg,
               const float* __restrict__ w_hh,   // (2048, 512) row-major
               const float* __restrict__ w_ih,   // (2048, 1)
               const float* __restrict__ b_ih,   // (2048,)
               const float* __restrict__ b_hh,   // (2048,)
               int s)
{
    __shared__ float  sW[32 * 128];      // [kk][col], col = gate*32 + j
    __shared__ float2 sH2[32 * 33];      // [kk][bi], value duplicated (v,v); +1 pad

    const float* __restrict__ h_in  = g_h[s & 1];
    float*       __restrict__ h_out = g_h[(s & 1) ^ 1];

    const int t  = threadIdx.x;
    const int k0 = blockIdx.x * 32;
    const int b0 = blockIdx.y * 32;

    const int cc  = t & 15;        // col-pair index 0..15
    const int bg  = t >> 4;        // batch group 0..15
    const int bi0 = bg * 2;

    // ---- accumulator init: bias + x_t * w_ih ----
    unsigned long long acc[2][4];
    const float x0 = (float)trg[(b0 + bi0    ) * TLEN + s];
    const float x1 = (float)trg[(b0 + bi0 + 1) * TLEN + s];
#pragma unroll
    for (int g = 0; g < 4; g++) {
        int r = g * HDIM + k0 + 2 * cc;
        float2 bi2 = *(const float2*)(b_ih + r);
        float2 bh2 = *(const float2*)(b_hh + r);
        float2 wi2 = *(const float2*)(w_ih + r);
        float blo = bi2.x + bh2.x, bhi = bi2.y + bh2.y;
        acc[0][g] = pack2(fmaf(x0, wi2.x, blo), fmaf(x0, wi2.y, bhi));
        acc[1][g] = pack2(fmaf(x1, wi2.x, blo), fmaf(x1, wi2.y, bhi));
    }

    // ---- W / h staging index precompute ----
    const int r128 = t >> 1;                       // tile col 0..127
    const int hf   = t & 1;                        // half of the 32-wide K chunk
    const int grow = (r128 >> 5) * HDIM + k0 + (r128 & 31);
    const float4* __restrict__ Wrow = (const float4*)(w_hh + (size_t)grow * HDIM);

    const int hbi = t >> 3;                        // 0..31 batch row for h staging
    const int hk0 = (t & 7) * 4;

    const unsigned long long* sWu = (const unsigned long long*)sW;
    const unsigned long long* sHu = (const unsigned long long*)sH2;

    for (int kc = 0; kc < HDIM; kc += 32) {
#pragma unroll
        for (int q = 0; q < 4; q++) {
            float4 v = Wrow[(kc + hf * 16) / 4 + q];
            int kl = hf * 16 + q * 4;
            sW[(kl + 0) * 128 + r128] = v.x;
            sW[(kl + 1) * 128 + r128] = v.y;
            sW[(kl + 2) * 128 + r128] = v.z;
            sW[(kl + 3) * 128 + r128] = v.w;
        }
        float4 hv = *(const float4*)(h_in + (b0 + hbi) * HDIM + kc + hk0);
        sH2[(hk0 + 0) * 33 + hbi] = make_float2(hv.x, hv.x);
        sH2[(hk0 + 1) * 33 + hbi] = make_float2(hv.y, hv.y);
        sH2[(hk0 + 2) * 33 + hbi] = make_float2(hv.z, hv.z);
        sH2[(hk0 + 3) * 33 + hbi] = make_float2(hv.w, hv.w);
        __syncthreads();

#pragma unroll 8
        for (int kk = 0; kk < 32; kk++) {
            unsigned long long h0 = sHu[kk * 33 + bi0];
            unsigned long long h1 = sHu[kk * 33 + bi0 + 1];
#pragma unroll
            for (int g = 0; g < 4; g++) {
                unsigned long long w = sWu[kk * 64 + g * 16 + cc];
                ffma2(acc[0][g], w, h0);
                ffma2(acc[1][g], w, h1);
            }
        }
        __syncthreads();
    }

    // ---- pointwise LSTM update (gate order i, f, g, o) ----
#pragma unroll
    for (int bb = 0; bb < 2; bb++) {
        int b = b0 + bi0 + bb;
        float iv0, iv1, fv0, fv1, gv0, gv1, ov0, ov1;
        unpack2(acc[bb][0], iv0, iv1);
        unpack2(acc[bb][1], fv0, fv1);
        unpack2(acc[bb][2], gv0, gv1);
        unpack2(acc[bb][3], ov0, ov1);

        size_t off = (size_t)b * HDIM + k0 + 2 * cc;
        float2 cold = *(const float2*)(g_c + off);

        float i0 = sigmoidf_(iv0), f0 = sigmoidf_(fv0), gg0 = tanhf_(gv0), o0 = sigmoidf_(ov0);
        float i1 = sigmoidf_(iv1), f1 = sigmoidf_(fv1), gg1 = tanhf_(gv1), o1 = sigmoidf_(ov1);
        float cn0 = fmaf(f0, cold.x, i0 * gg0);
        float cn1 = fmaf(f1, cold.y, i1 * gg1);
        float hn0 = o0 * tanhf_(cn0);
        float hn1 = o1 * tanhf_(cn1);

        *(float2*)(g_c + off)   = make_float2(cn0, cn1);
        *(float2*)(h_out + off) = make_float2(hn0, hn1);
    }
}

// ============================================================================
// Generic fused GEMM head: C[M,N] = A[M,K] @ W[N,K]^T + bias, optional ReLU.
// Same microkernel shape: 32(M) x 128(N) tile, 256 threads, FFMA2.
// asel: 0 -> A = g_h[1] (final hidden), 1 -> A = g_z.
// ============================================================================
__global__ __launch_bounds__(256)
void fc_gemm(int asel,
             const float* __restrict__ W,
             const float* __restrict__ bias,
             float* __restrict__ C,
             int K, int N, int do_relu)
{
    __shared__ float  sW[32 * 128];
    __shared__ float2 sH2[32 * 33];

    const float* __restrict__ A = (asel == 0) ? &g_h[1][0] : &g_z[0];

    const int t  = threadIdx.x;
    const int n0 = blockIdx.x * 128;
    const int m0 = blockIdx.y * 32;

    const int cc  = t & 15;
    const int bg  = t >> 4;
    const int bi0 = bg * 2;

    unsigned long long acc[2][4];
#pragma unroll
    for (int g = 0; g < 4; g++) {
        float2 b2 = *(const float2*)(bias + n0 + g * 32 + 2 * cc);
        acc[0][g] = pack2(b2.x, b2.y);
        acc[1][g] = pack2(b2.x, b2.y);
    }

    const int r128 = t >> 1;
    const int hf   = t & 1;
    const float4* __restrict__ Wrow = (const float4*)(W + (size_t)(n0 + r128) * K);

    const int hbi = t >> 3;
    const int hk0 = (t & 7) * 4;

    const unsigned long long* sWu = (const unsigned long long*)sW;
    const unsigned long long* sHu = (const unsigned long long*)sH2;

    for (int kc = 0; kc < K; kc += 32) {
#pragma unroll
        for (int q = 0; q < 4; q++) {
            float4 v = Wrow[(kc + hf * 16) / 4 + q];
            int kl = hf * 16 + q * 4;
            sW[(kl + 0) * 128 + r128] = v.x;
            sW[(kl + 1) * 128 + r128] = v.y;
            sW[(kl + 2) * 128 + r128] = v.z;
            sW[(kl + 3) * 128 + r128] = v.w;
        }
        float4 hv = *(const float4*)(A + (size_t)(m0 + hbi) * K + kc + hk0);
        sH2[(hk0 + 0) * 33 + hbi] = make_float2(hv.x, hv.x);
        sH2[(hk0 + 1) * 33 + hbi] = make_float2(hv.y, hv.y);
        sH2[(hk0 + 2) * 33 + hbi] = make_float2(hv.z, hv.z);
        sH2[(hk0 + 3) * 33 + hbi] = make_float2(hv.w, hv.w);
        __syncthreads();

#pragma unroll 8
        for (int kk = 0; kk < 32; kk++) {
            unsigned long long h0 = sHu[kk * 33 + bi0];
            unsigned long long h1 = sHu[kk * 33 + bi0 + 1];
#pragma unroll
            for (int g = 0; g < 4; g++) {
                unsigned long long w = sWu[kk * 64 + g * 16 + cc];
                ffma2(acc[0][g], w, h0);
                ffma2(acc[1][g], w, h1);
            }
        }
        __syncthreads();
    }

#pragma unroll
    for (int bb = 0; bb < 2; bb++) {
        int m = m0 + bi0 + bb;
#pragma unroll
        for (int g = 0; g < 4; g++) {
            float lo, hi;
            unpack2(acc[bb][g], lo, hi);
            if (do_relu) { lo = fmaxf(lo, 0.0f); hi = fmaxf(hi, 0.0f); }
            *(float2*)(C + (size_t)m * N + n0 + g * 32 + 2 * cc) = make_float2(lo, hi);
        }
    }
}

// ============================================================================
extern "C" void kernel_launch(void* const* d_in, const int* in_sizes, int n_in,
                              void* d_out, int out_size) {
    // metadata order: x, hidden, trg, w_ih, w_hh, b_ih, b_hh, fc1_w, fc1_b, fc2_w, fc2_b
    const int*   trg   = (const int*)  d_in[2];
    const float* w_ih  = (const float*)d_in[3];
    const float* w_hh  = (const float*)d_in[4];
    const float* b_ih  = (const float*)d_in[5];
    const float* b_hh  = (const float*)d_in[6];
    const float* fc1_w = (const float*)d_in[7];
    const float* fc1_b = (const float*)d_in[8];
    const float* fc2_w = (const float*)d_in[9];
    const float* fc2_b = (const float*)d_in[10];
    float* out = (float*)d_out;

    zero_state<<<128, 256>>>();

    dim3 sgrid(HDIM / 32, BATCH / 32);   // (16, 8) = 128 CTAs
    for (int s = 0; s < NSTEPS; s++) {
        lstm_step<<<sgrid, 256>>>(trg, w_hh, w_ih, b_ih, b_hh, s);
    }

    // z = relu(h_last @ fc1_w^T + fc1_b): writes g_z
    void* zptr_sym = nullptr;
    cudaGetSymbolAddress(&zptr_sym, g_z);
    float* zptr = (float*)zptr_sym;
    fc_gemm<<<dim3(FC1_N / 128, BATCH / 32), 256>>>(
        0, fc1_w, fc1_b, zptr, HDIM, FC1_N, 1);

    // out = z @ fc2_w^T + fc2_b
    fc_gemm<<<dim3(FC2_N / 128, BATCH / 32), 256>>>(
        1, fc2_w, fc2_b, out, FC1_N, FC2_N, 0);
}

// round 3
// speedup vs baseline: 1.2328x; 1.2328x over previous
#include <cuda_runtime.h>

#define HDIM 512
#define BATCH 256
#define TLEN 512
#define NSTEPS 511          // steps use trg[:, 0..510]
#define FC1_N 1024
#define FC2_N 32000
#define KHALF 256
#define NTILES 64           // 16 k-tiles x 4 b-tiles

// -------- persistent device scratch (no allocations allowed) --------
__device__ float g_h[2][BATCH * HDIM];     // hidden, [b][k], double buffered
__device__ float g_ht[2][HDIM * BATCH];    // hidden transposed, [k][b]
__device__ float g_c[BATCH * HDIM];        // cell state
__device__ float g_z[BATCH * FC1_N];       // fc1 output
__device__ unsigned long long g_part[NTILES * 16 * 256];  // split-K partials
__device__ unsigned int g_cnt[NTILES];     // arrival counters
__device__ unsigned int g_rel[NTILES];     // release counters

// -------- packed fp32x2 helpers (Blackwell FFMA2 path) --------
__device__ __forceinline__ unsigned long long pack2(float lo, float hi) {
    unsigned long long r;
    asm("mov.b64 %0, {%1, %2};" : "=l"(r) : "f"(lo), "f"(hi));
    return r;
}
__device__ __forceinline__ void unpack2(unsigned long long v, float& lo, float& hi) {
    asm("mov.b64 {%0, %1}, %2;" : "=f"(lo), "=f"(hi) : "l"(v));
}
__device__ __forceinline__ void ffma2(unsigned long long& d,
                                      unsigned long long a, unsigned long long b) {
    asm("fma.rn.f32x2 %0, %1, %2, %0;" : "+l"(d) : "l"(a), "l"(b));
}
__device__ __forceinline__ unsigned int ld_acq(const unsigned int* p) {
    unsigned int v;
    asm volatile("ld.global.acquire.gpu.b32 %0, [%1];" : "=r"(v) : "l"(p));
    return v;
}

__device__ __forceinline__ float sigmoidf_(float x) {
    return 1.0f / (1.0f + expf(-x));
}
__device__ __forceinline__ float tanhf_(float x) {
    return 1.0f - 2.0f / (expf(2.0f * x) + 1.0f);
}

// -------- init: zero h[0], ht[0], c, and split-K counters --------
__global__ void zero_state() {
    int i = blockIdx.x * blockDim.x + threadIdx.x;
    int stride = gridDim.x * blockDim.x;
    for (int j = i; j < BATCH * HDIM; j += stride) {
        g_h[0][j] = 0.0f;
        g_ht[0][j] = 0.0f;
        g_c[j] = 0.0f;
    }
    if (i < NTILES) { g_cnt[i] = 0u; g_rel[i] = 0u; }
}

// ============================================================================
// One LSTM timestep, split-K by 2 with in-kernel cross-CTA combine.
// Grid (16 k-tiles, 4 b-tiles, 2 K-halves) = 128 CTAs, 256 threads.
// CTA output tile: 64 batch x (4 gates x 32 k), K-half = 256.
// Thread: 4 batch x 2 k x 4 gates = 16 fp32x2 accumulators.
// First CTA of a (kx, by) pair to finish writes partials + release and exits;
// the second combines, applies the LSTM pointwise, writes h (both layouts).
// ============================================================================
__global__ __launch_bounds__(256)
void lstm_step(const int* __restrict__ trg,
               const float* __restrict__ w_hh,   // (2048, 512) row-major
               const float* __restrict__ w_ih,   // (2048, 1)
               const float* __restrict__ b_ih,   // (2048,)
               const float* __restrict__ b_hh,   // (2048,)
               int s)
{
    __shared__ float  sW[32 * 128];      // [kk][col], col = gate*32 + j
    __shared__ float2 sH2[32 * 65];      // [kk][b], duplicated (v,v), +1 pad
    __shared__ unsigned int s_order;

    const float* __restrict__ ht_in  = g_ht[s & 1];
    float*       __restrict__ h_out  = g_h[(s & 1) ^ 1];
    float*       __restrict__ ht_out = g_ht[(s & 1) ^ 1];

    const int t  = threadIdx.x;
    const int k0 = blockIdx.x * 32;
    const int b0 = blockIdx.y * 64;
    const int z  = blockIdx.z;                 // K-half
    const int tile = blockIdx.y * 16 + blockIdx.x;
    const int kbase = z * KHALF;

    const int cc = t & 15;         // k-pair index 0..15
    const int bg = t >> 4;         // batch group 0..15 (4 rows each)
    const int hrow = 4 * bg;

    // ---- accumulator init: z==0 carries bias + x*w_ih, z==1 starts at 0 ----
    unsigned long long acc[4][4];
    if (z == 0) {
        float blo[4], bhi[4], wlo[4], whi[4];
#pragma unroll
        for (int g = 0; g < 4; g++) {
            int r = g * HDIM + k0 + 2 * cc;
            float2 bi2 = *(const float2*)(b_ih + r);
            float2 bh2 = *(const float2*)(b_hh + r);
            float2 wi2 = *(const float2*)(w_ih + r);
            blo[g] = bi2.x + bh2.x; bhi[g] = bi2.y + bh2.y;
            wlo[g] = wi2.x;         whi[g] = wi2.y;
        }
#pragma unroll
        for (int bb = 0; bb < 4; bb++) {
            float x = (float)trg[(b0 + hrow + bb) * TLEN + s];
#pragma unroll
            for (int g = 0; g < 4; g++)
                acc[bb][g] = pack2(fmaf(x, wlo[g], blo[g]), fmaf(x, whi[g], bhi[g]));
        }
    } else {
#pragma unroll
        for (int bb = 0; bb < 4; bb++)
#pragma unroll
            for (int g = 0; g < 4; g++) acc[bb][g] = 0ULL;
    }

    // ---- staging index precompute ----
    const int r128 = t >> 1;                         // tile col 0..127
    const int hf   = t & 1;
    const int grow = (r128 >> 5) * HDIM + k0 + (r128 & 31);
    const float4* __restrict__ Wrow = (const float4*)(w_hh + (size_t)grow * HDIM);

    const int skk = t >> 3;                          // 0..31: kk row for h staging
    const int ssg = t & 7;                           // 0..7 : 4-batch segment

    const unsigned long long* sWu = (const unsigned long long*)sW;
    const unsigned long long* sHu = (const unsigned long long*)sH2;

    for (int kc = 0; kc < KHALF; kc += 32) {
        if (kc) __syncthreads();
        // W tile: [kk][col]
#pragma unroll
        for (int q = 0; q < 4; q++) {
            float4 v = Wrow[(kbase + kc + hf * 16) / 4 + q];
            int kl = hf * 16 + q * 4;
            sW[(kl + 0) * 128 + r128] = v.x;
            sW[(kl + 1) * 128 + r128] = v.y;
            sW[(kl + 2) * 128 + r128] = v.z;
            sW[(kl + 3) * 128 + r128] = v.w;
        }
        // h tile from transposed layout (coalesced): ht[k][b]
        {
            const float* hr = ht_in + (size_t)(kbase + kc + skk) * BATCH + b0;
            float4 h0 = *(const float4*)(hr + ssg * 4);
            float4 h1 = *(const float4*)(hr + 32 + ssg * 4);
            sH2[skk * 65 + ssg * 4 + 0] = make_float2(h0.x, h0.x);
            sH2[skk * 65 + ssg * 4 + 1] = make_float2(h0.y, h0.y);
            sH2[skk * 65 + ssg * 4 + 2] = make_float2(h0.z, h0.z);
            sH2[skk * 65 + ssg * 4 + 3] = make_float2(h0.w, h0.w);
            sH2[skk * 65 + 32 + ssg * 4 + 0] = make_float2(h1.x, h1.x);
            sH2[skk * 65 + 32 + ssg * 4 + 1] = make_float2(h1.y, h1.y);
            sH2[skk * 65 + 32 + ssg * 4 + 2] = make_float2(h1.z, h1.z);
            sH2[skk * 65 + 32 + ssg * 4 + 3] = make_float2(h1.w, h1.w);
        }
        __syncthreads();

        // ---- inner: explicit 1-deep register prefetch ----
        unsigned long long hc[4], wc[4], hn[4], wn[4];
#pragma unroll
        for (int bb = 0; bb < 4; bb++) hc[bb] = sHu[hrow + bb];
#pragma unroll
        for (int g = 0; g < 4; g++)   wc[g]  = sWu[g * 16 + cc];
#pragma unroll 4
        for (int kk = 0; kk < 31; kk++) {
#pragma unroll
            for (int bb = 0; bb < 4; bb++) hn[bb] = sHu[(kk + 1) * 65 + hrow + bb];
#pragma unroll
            for (int g = 0; g < 4; g++)   wn[g]  = sWu[(kk + 1) * 64 + g * 16 + cc];
#pragma unroll
            for (int bb = 0; bb < 4; bb++)
#pragma unroll
                for (int g = 0; g < 4; g++)
                    ffma2(acc[bb][g], wc[g], hc[bb]);
#pragma unroll
            for (int i = 0; i < 4; i++) { hc[i] = hn[i]; wc[i] = wn[i]; }
        }
#pragma unroll
        for (int bb = 0; bb < 4; bb++)
#pragma unroll
            for (int g = 0; g < 4; g++)
                ffma2(acc[bb][g], wc[g], hc[bb]);
    }

    // ---- split-K rendezvous ----
    if (t == 0) s_order = atomicAdd(&g_cnt[tile], 1u);
    __syncthreads();
    const bool first = (s_order == (unsigned)(2 * s));

    unsigned long long* part = g_part + (size_t)tile * 16 * 256;

    if (first) {
#pragma unroll
        for (int bb = 0; bb < 4; bb++)
#pragma unroll
            for (int g = 0; g < 4; g++)
                part[(bb * 4 + g) * 256 + t] = acc[bb][g];
        __threadfence();
        __syncthreads();
        if (t == 0) atomicAdd(&g_rel[tile], 1u);
        return;
    }

    // second arriver: wait for partner's partials
    if (t == 0) {
        while (ld_acq(&g_rel[tile]) < (unsigned)(s + 1)) { }
    }
    __syncthreads();

#pragma unroll
    for (int bb = 0; bb < 4; bb++)
#pragma unroll
        for (int g = 0; g < 4; g++) {
            unsigned long long o = part[(bb * 4 + g) * 256 + t];
            float al, ah, ol, oh;
            unpack2(acc[bb][g], al, ah);
            unpack2(o, ol, oh);
            acc[bb][g] = pack2(al + ol, ah + oh);
        }

    // ---- pointwise LSTM update (gate order i, f, g, o) ----
    float hn_lo[4], hn_hi[4];
#pragma unroll
    for (int bb = 0; bb < 4; bb++) {
        int b = b0 + hrow + bb;
        float iv0, iv1, fv0, fv1, gv0, gv1, ov0, ov1;
        unpack2(acc[bb][0], iv0, iv1);
        unpack2(acc[bb][1], fv0, fv1);
        unpack2(acc[bb][2], gv0, gv1);
        unpack2(acc[bb][3], ov0, ov1);

        size_t off = (size_t)b * HDIM + k0 + 2 * cc;
        float2 cold = *(const float2*)(g_c + off);

        float i0 = sigmoidf_(iv0), f0 = sigmoidf_(fv0), gg0 = tanhf_(gv0), o0 = sigmoidf_(ov0);
        float i1 = sigmoidf_(iv1), f1 = sigmoidf_(fv1), gg1 = tanhf_(gv1), o1 = sigmoidf_(ov1);
        float cn0 = fmaf(f0, cold.x, i0 * gg0);
        float cn1 = fmaf(f1, cold.y, i1 * gg1);
        float h0 = o0 * tanhf_(cn0);
        float h1 = o1 * tanhf_(cn1);

        *(float2*)(g_c + off)   = make_float2(cn0, cn1);
        *(float2*)(h_out + off) = make_float2(h0, h1);
        hn_lo[bb] = h0; hn_hi[bb] = h1;
    }
    // transposed h for next step's coalesced staging: ht[k][b]
    {
        int col0 = k0 + 2 * cc;
        float4 v0 = make_float4(hn_lo[0], hn_lo[1], hn_lo[2], hn_lo[3]);
        float4 v1 = make_float4(hn_hi[0], hn_hi[1], hn_hi[2], hn_hi[3]);
        *(float4*)(ht_out + (size_t)col0 * BATCH + b0 + hrow)       = v0;
        *(float4*)(ht_out + (size_t)(col0 + 1) * BATCH + b0 + hrow) = v1;
    }
}

// ============================================================================
// Generic fused GEMM head: C[M,N] = A[M,K] @ W[N,K]^T + bias, optional ReLU.
// 32(M) x 128(N) tile, 256 threads, FFMA2. asel: 0 -> A = g_h[1], 1 -> A = g_z.
// ============================================================================
__global__ __launch_bounds__(256)
void fc_gemm(int asel,
             const float* __restrict__ W,
             const float* __restrict__ bias,
             float* __restrict__ C,
             int K, int N, int do_relu)
{
    __shared__ float  sW[32 * 128];
    __shared__ float2 sH2[32 * 33];

    const float* __restrict__ A = (asel == 0) ? &g_h[1][0] : &g_z[0];

    const int t  = threadIdx.x;
    const int n0 = blockIdx.x * 128;
    const int m0 = blockIdx.y * 32;

    const int cc  = t & 15;
    const int bg  = t >> 4;
    const int bi0 = bg * 2;

    unsigned long long acc[2][4];
#pragma unroll
    for (int g = 0; g < 4; g++) {
        float2 b2 = *(const float2*)(bias + n0 + g * 32 + 2 * cc);
        acc[0][g] = pack2(b2.x, b2.y);
        acc[1][g] = pack2(b2.x, b2.y);
    }

    const int r128 = t >> 1;
    const int hf   = t & 1;
    const float4* __restrict__ Wrow = (const float4*)(W + (size_t)(n0 + r128) * K);

    const int hbi = t >> 3;
    const int hk0 = (t & 7) * 4;

    const unsigned long long* sWu = (const unsigned long long*)sW;
    const unsigned long long* sHu = (const unsigned long long*)sH2;

    for (int kc = 0; kc < K; kc += 32) {
        if (kc) __syncthreads();
#pragma unroll
        for (int q = 0; q < 4; q++) {
            float4 v = Wrow[(kc + hf * 16) / 4 + q];
            int kl = hf * 16 + q * 4;
            sW[(kl + 0) * 128 + r128] = v.x;
            sW[(kl + 1) * 128 + r128] = v.y;
            sW[(kl + 2) * 128 + r128] = v.z;
            sW[(kl + 3) * 128 + r128] = v.w;
        }
        float4 hv = *(const float4*)(A + (size_t)(m0 + hbi) * K + kc + hk0);
        sH2[(hk0 + 0) * 33 + hbi] = make_float2(hv.x, hv.x);
        sH2[(hk0 + 1) * 33 + hbi] = make_float2(hv.y, hv.y);
        sH2[(hk0 + 2) * 33 + hbi] = make_float2(hv.z, hv.z);
        sH2[(hk0 + 3) * 33 + hbi] = make_float2(hv.w, hv.w);
        __syncthreads();

#pragma unroll 8
        for (int kk = 0; kk < 32; kk++) {
            unsigned long long h0 = sHu[kk * 33 + bi0];
            unsigned long long h1 = sHu[kk * 33 + bi0 + 1];
#pragma unroll
            for (int g = 0; g < 4; g++) {
                unsigned long long w = sWu[kk * 64 + g * 16 + cc];
                ffma2(acc[0][g], w, h0);
                ffma2(acc[1][g], w, h1);
            }
        }
    }

#pragma unroll
    for (int bb = 0; bb < 2; bb++) {
        int m = m0 + bi0 + bb;
#pragma unroll
        for (int g = 0; g < 4; g++) {
            float lo, hi;
            unpack2(acc[bb][g], lo, hi);
            if (do_relu) { lo = fmaxf(lo, 0.0f); hi = fmaxf(hi, 0.0f); }
            *(float2*)(C + (size_t)m * N + n0 + g * 32 + 2 * cc) = make_float2(lo, hi);
        }
    }
}

// ============================================================================
extern "C" void kernel_launch(void* const* d_in, const int* in_sizes, int n_in,
                              void* d_out, int out_size) {
    // metadata order: x, hidden, trg, w_ih, w_hh, b_ih, b_hh, fc1_w, fc1_b, fc2_w, fc2_b
    const int*   trg   = (const int*)  d_in[2];
    const float* w_ih  = (const float*)d_in[3];
    const float* w_hh  = (const float*)d_in[4];
    const float* b_ih  = (const float*)d_in[5];
    const float* b_hh  = (const float*)d_in[6];
    const float* fc1_w = (const float*)d_in[7];
    const float* fc1_b = (const float*)d_in[8];
    const float* fc2_w = (const float*)d_in[9];
    const float* fc2_b = (const float*)d_in[10];
    float* out = (float*)d_out;

    zero_state<<<128, 256>>>();

    dim3 sgrid(HDIM / 32, BATCH / 64, 2);   // (16, 4, 2) = 128 CTAs
    for (int s = 0; s < NSTEPS; s++) {
        lstm_step<<<sgrid, 256>>>(trg, w_hh, w_ih, b_ih, b_hh, s);
    }

    // z = relu(h_last @ fc1_w^T + fc1_b)
    void* zptr_sym = nullptr;
    cudaGetSymbolAddress(&zptr_sym, g_z);
    float* zptr = (float*)zptr_sym;
    fc_gemm<<<dim3(FC1_N / 128, BATCH / 32), 256>>>(
        0, fc1_w, fc1_b, zptr, HDIM, FC1_N, 1);

    // out = z @ fc2_w^T + fc2_b
    fc_gemm<<<dim3(FC2_N / 128, BATCH / 32), 256>>>(
        1, fc2_w, fc2_b, out, FC1_N, FC2_N, 0);
}